// round 9
// baseline (speedup 1.0000x reference)
#include <cuda_runtime.h>
#include <cstdint>

// ---------------------------------------------------------------------------
// Problem constants
// ---------------------------------------------------------------------------
#define GG      8
#define LL      4096
#define CC      256
#define NST     8
#define RNK     16
#define DEPTHN  4
#define NROWS   (GG*LL)
#define LCH     64
#define NCH     (LL/LCH)

// ---------------------------------------------------------------------------
// Scratch (device globals) — referenced ONLY from device code
// ---------------------------------------------------------------------------
__device__ float g_x    [NROWS*CC];
__device__ float g_xn   [NROWS*CC];
__device__ float g_xz   [NROWS*2*CC];
__device__ float g_xc   [2*NROWS*CC];
__device__ float g_xdbl [2*NROWS*32];
__device__ float g_ydir [2*NROWS*CC];
__device__ float g_hloc [2*GG*NCH*CC*NST];
__device__ float g_hini [2*GG*NCH*CC*NST];
__device__ float g_S    [2*GG*NCH*CC];
__device__ float g_win  [DEPTHN*2*CC*CC];
__device__ float g_wxp  [DEPTHN*32*CC];
__device__ float g_wout [DEPTHN*CC*CC];

__device__ __forceinline__ unsigned f2tf(float x) {
    unsigned r;
    asm("cvt.rna.tf32.f32 %0, %1;" : "=r"(r) : "f"(x));
    return r;
}
__device__ __forceinline__ float tf32r(float x) { return __uint_as_float(f2tf(x)); }

// ---------------------------------------------------------------------------
// one-shot weight prep: round all layers' GEMM weights to tf32
// ---------------------------------------------------------------------------
#define NIN  (DEPTHN*2*CC*CC)
#define NXP  (DEPTHN*32*CC)
#define NOUT (DEPTHN*CC*CC)
__global__ void wprep(const float* __restrict__ inpw,
                      const float* __restrict__ xpw,
                      const float* __restrict__ outw) {
    int i = blockIdx.x * 256 + threadIdx.x;
    if (i < NIN)                    g_win[i]          = tf32r(inpw[i]);
    else if (i < NIN + NXP)         g_wxp[i - NIN]    = tf32r(xpw[i - NIN]);
    else if (i < NIN + NXP + NOUT)  g_wout[i-NIN-NXP] = tf32r(outw[i-NIN-NXP]);
}

// ---------------------------------------------------------------------------
// mean + transpose: data (B,C,HW) -> g_x (g,l,c)
// ---------------------------------------------------------------------------
__global__ void mean_kernel(const float* __restrict__ data,
                            const int* __restrict__ rl) {
    __shared__ float tile[32][33];
    int g  = blockIdx.z;
    int c0 = blockIdx.y * 32;
    int l0 = blockIdx.x * 32;
    int off = 0;
    for (int i = 0; i < g; i++) off += rl[i];
    int cnt = rl[g];
    float inv = 1.0f / (float)cnt;
    for (int cc = threadIdx.y; cc < 32; cc += 8) {
        int c = c0 + cc;
        int l = l0 + threadIdx.x;
        float s = 0.f;
        for (int a = 0; a < cnt; a++)
            s += data[((size_t)(off + a) * CC + c) * LL + l];
        tile[cc][threadIdx.x] = s * inv;
    }
    __syncthreads();
    for (int lc = threadIdx.y; lc < 32; lc += 8) {
        int l = l0 + lc;
        int c = c0 + threadIdx.x;
        g_x[((size_t)g * LL + l) * CC + c] = tile[threadIdx.x][lc];
    }
}

__global__ void out_transpose(float* __restrict__ out) {
    __shared__ float tile[32][33];
    int g  = blockIdx.z;
    int c0 = blockIdx.y * 32;
    int l0 = blockIdx.x * 32;
    for (int lc = threadIdx.y; lc < 32; lc += 8)
        tile[threadIdx.x][lc] = g_x[((size_t)g * LL + l0 + lc) * CC + c0 + threadIdx.x];
    __syncthreads();
    for (int cc = threadIdx.y; cc < 32; cc += 8)
        out[((size_t)g * CC + c0 + cc) * LL + l0 + threadIdx.x] = tile[cc][threadIdx.x];
}

// ---------------------------------------------------------------------------
// Fused LayerNorm (warp per row).
// POST: x := LN(g_xn)*wp+bp + g_x ; PRE: g_xn := tf32(LN(x)*wq+bq)
// ---------------------------------------------------------------------------
template<int POST, int PRE>
__global__ void ln_fused(const float* __restrict__ wp, const float* __restrict__ bp,
                         const float* __restrict__ wq, const float* __restrict__ bq) {
    int row  = blockIdx.x * 8 + (threadIdx.x >> 5);
    int lane = threadIdx.x & 31;
    float v[8];
    if (POST) {
        const float* r = g_xn + (size_t)row * CC;
        float s = 0.f, s2 = 0.f;
#pragma unroll
        for (int k = 0; k < 8; k++) {
            v[k] = r[k * 32 + lane];
            s += v[k]; s2 += v[k] * v[k];
        }
#pragma unroll
        for (int o = 16; o; o >>= 1) {
            s  += __shfl_xor_sync(0xffffffffu, s,  o);
            s2 += __shfl_xor_sync(0xffffffffu, s2, o);
        }
        float mu  = s * (1.0f / CC);
        float var = s2 * (1.0f / CC) - mu * mu;
        float inv = rsqrtf(var + 1e-5f);
#pragma unroll
        for (int k = 0; k < 8; k++) {
            int cc = k * 32 + lane;
            v[k] = (v[k] - mu) * inv * wp[cc] + bp[cc] + g_x[(size_t)row * CC + cc];
            g_x[(size_t)row * CC + cc] = v[k];
        }
    } else {
        const float* r = g_x + (size_t)row * CC;
#pragma unroll
        for (int k = 0; k < 8; k++) v[k] = r[k * 32 + lane];
    }
    if (PRE) {
        float s = 0.f, s2 = 0.f;
#pragma unroll
        for (int k = 0; k < 8; k++) { s += v[k]; s2 += v[k] * v[k]; }
#pragma unroll
        for (int o = 16; o; o >>= 1) {
            s  += __shfl_xor_sync(0xffffffffu, s,  o);
            s2 += __shfl_xor_sync(0xffffffffu, s2, o);
        }
        float mu  = s * (1.0f / CC);
        float var = s2 * (1.0f / CC) - mu * mu;
        float inv = rsqrtf(var + 1e-5f);
#pragma unroll
        for (int k = 0; k < 8; k++) {
            int cc = k * 32 + lane;
            g_xn[(size_t)row * CC + cc] = tf32r((v[k] - mu) * inv * wq[cc] + bq[cc]);
        }
    }
}

// ---------------------------------------------------------------------------
// cp.async helpers
// ---------------------------------------------------------------------------
__device__ __forceinline__ void cp16(void* dst_smem, const void* src) {
    uint32_t d = (uint32_t)__cvta_generic_to_shared(dst_smem);
    asm volatile("cp.async.cg.shared.global [%0], [%1], 16;" :: "r"(d), "l"(src));
}
#define CP_COMMIT() asm volatile("cp.async.commit_group;" ::: "memory")
#define CP_WAIT(n)  asm volatile("cp.async.wait_group %0;" :: "n"(n) : "memory")

// ---------------------------------------------------------------------------
// 3-stage pipelined tf32 tensor-core GEMM (unchanged from R8 — 115 TF/s eff.)
// ---------------------------------------------------------------------------
template<int MODE, int BN>
__global__ void __launch_bounds__(256)
tc_gemm(int layer) {
    constexpr int BM = 128;
    constexpr int BK = 16;
    constexpr int SW = BK + 4;
    constexpr int KT = (MODE == 2) ? 32 : 16;
    constexpr bool CVT_A = (MODE == 1);
    constexpr int WARPS_N = (BN == 128) ? 4 : 1;
    constexpr int WARPS_M = 8 / WARPS_N;
    constexpr int WM = BM / WARPS_M;
    constexpr int WN = BN / WARPS_N;
    constexpr int MT = WM / 16;
    constexpr int NT = WN / 8;

    __shared__ float As[3][BM * SW];
    __shared__ float Bs[3][BN * SW];

    const int tid  = threadIdx.x;
    const int lane = tid & 31;
    const int warp = tid >> 5;
    const int bm   = blockIdx.y * BM;
    const int bn   = blockIdx.x * BN;
    const int wm   = (warp / WARPS_N) * WM;
    const int wn   = (warp % WARPS_N) * WN;

    const float* A0;
    const float* W;
    float* Cout;
    int Nn;
    if (MODE == 0)      { A0 = g_xn;  W = g_win + (size_t)layer * 2 * CC * CC;
                          Cout = g_xz;  Nn = 2 * CC; }
    else if (MODE == 1) { A0 = g_xc + (size_t)blockIdx.z * NROWS * CC;
                          W = g_wxp + (size_t)layer * 32 * CC;
                          Cout = g_xdbl + (size_t)blockIdx.z * NROWS * 32; Nn = 32; }
    else                { A0 = g_ydir; W = g_wout + (size_t)layer * CC * CC;
                          Cout = g_xn; Nn = CC; }

    auto stage = [&](int s, int kc) {
        const float* Ap = A0;
        if (MODE == 2 && kc >= 16) Ap = g_ydir + (size_t)NROWS * CC;
        const int k0 = (kc & 15) * BK;
        for (int idx = tid; idx < BM * 4; idx += 256) {
            int r = idx >> 2, q = idx & 3;
            cp16(&As[s][r * SW + q * 4], Ap + (size_t)(bm + r) * CC + k0 + q * 4);
        }
        for (int idx = tid; idx < BN * 4; idx += 256) {
            int r = idx >> 2, q = idx & 3;
            cp16(&Bs[s][r * SW + q * 4], W + (size_t)(bn + r) * CC + k0 + q * 4);
        }
    };

    float c[MT][NT][4];
#pragma unroll
    for (int i = 0; i < MT; i++)
#pragma unroll
        for (int j = 0; j < NT; j++)
#pragma unroll
            for (int q = 0; q < 4; q++) c[i][j][q] = 0.f;

    stage(0, 0); CP_COMMIT();
    stage(1, 1); CP_COMMIT();

#pragma unroll 1
    for (int kc = 0; kc < KT; kc++) {
        if (kc == KT - 1) { CP_WAIT(0); } else { CP_WAIT(1); }
        __syncthreads();

        const float* as_ = As[kc % 3];
        const float* bs_ = Bs[kc % 3];
#pragma unroll
        for (int ks = 0; ks < BK / 8; ks++) {
            const int kk = ks * 8 + (lane & 3);
            unsigned a[MT][4], bf[NT][2];
#pragma unroll
            for (int i = 0; i < MT; i++) {
                int r0 = wm + i * 16 + (lane >> 2);
                if (CVT_A) {
                    a[i][0] = f2tf(as_[r0 * SW + kk]);
                    a[i][1] = f2tf(as_[(r0 + 8) * SW + kk]);
                    a[i][2] = f2tf(as_[r0 * SW + kk + 4]);
                    a[i][3] = f2tf(as_[(r0 + 8) * SW + kk + 4]);
                } else {
                    a[i][0] = __float_as_uint(as_[r0 * SW + kk]);
                    a[i][1] = __float_as_uint(as_[(r0 + 8) * SW + kk]);
                    a[i][2] = __float_as_uint(as_[r0 * SW + kk + 4]);
                    a[i][3] = __float_as_uint(as_[(r0 + 8) * SW + kk + 4]);
                }
            }
#pragma unroll
            for (int j = 0; j < NT; j++) {
                int n0 = wn + j * 8 + (lane >> 2);
                bf[j][0] = __float_as_uint(bs_[n0 * SW + kk]);
                bf[j][1] = __float_as_uint(bs_[n0 * SW + kk + 4]);
            }
#pragma unroll
            for (int i = 0; i < MT; i++)
#pragma unroll
                for (int j = 0; j < NT; j++) {
                    asm volatile(
                        "mma.sync.aligned.m16n8k8.row.col.f32.tf32.tf32.f32 "
                        "{%0,%1,%2,%3}, {%4,%5,%6,%7}, {%8,%9}, {%0,%1,%2,%3};"
                        : "+f"(c[i][j][0]), "+f"(c[i][j][1]),
                          "+f"(c[i][j][2]), "+f"(c[i][j][3])
                        : "r"(a[i][0]), "r"(a[i][1]), "r"(a[i][2]), "r"(a[i][3]),
                          "r"(bf[j][0]), "r"(bf[j][1]));
                }
        }
        __syncthreads();
        if (kc + 2 < KT) { stage((kc + 2) % 3, kc + 2); CP_COMMIT(); }
    }

#pragma unroll
    for (int i = 0; i < MT; i++) {
        int r0 = bm + wm + i * 16 + (lane >> 2);
#pragma unroll
        for (int j = 0; j < NT; j++) {
            int c0 = bn + wn + j * 8 + 2 * (lane & 3);
            *(float2*)(Cout + (size_t)r0 * Nn + c0)       = make_float2(c[i][j][0], c[i][j][1]);
            *(float2*)(Cout + (size_t)(r0 + 8) * Nn + c0) = make_float2(c[i][j][2], c[i][j][3]);
        }
    }
}

// ---------------------------------------------------------------------------
// Depthwise causal conv (k=4) + SiLU, float4 over channels
// ---------------------------------------------------------------------------
__global__ void conv_silu_kernel(const float* __restrict__ w,
                                 const float* __restrict__ b) {
    size_t i  = (size_t)blockIdx.x * 256 + threadIdx.x;
    int d0    = (int)(i & 63) * 4;
    size_t rg = i >> 6;
    int dir   = rg >= (size_t)NROWS;
    size_t row = rg - (size_t)dir * NROWS;
    int l = (int)(row & (LL - 1));
    int g = (int)(row >> 12);

    float4 wt[4];
#pragma unroll
    for (int j = 0; j < 4; j++) wt[j] = *(const float4*)(w + (d0 + j) * 4);
    float4 acc = *(const float4*)(b + d0);

#pragma unroll
    for (int k = 0; k < 4; k++) {
        int ls = (dir == 0) ? (l - 3 + k) : (l + 3 - k);
        if (ls >= 0 && ls < LL) {
            const float4 xv = *(const float4*)(g_xz + ((size_t)g * LL + ls) * (2 * CC) + d0);
            acc.x += ((const float*)&wt[0])[k] * xv.x;
            acc.y += ((const float*)&wt[1])[k] * xv.y;
            acc.z += ((const float*)&wt[2])[k] * xv.z;
            acc.w += ((const float*)&wt[3])[k] * xv.w;
        }
    }
    acc.x = acc.x / (1.0f + __expf(-acc.x));
    acc.y = acc.y / (1.0f + __expf(-acc.y));
    acc.z = acc.z / (1.0f + __expf(-acc.z));
    acc.w = acc.w / (1.0f + __expf(-acc.w));
    *(float4*)(g_xc + (size_t)dir * NROWS * CC + row * CC + d0) = acc;
}

// ---------------------------------------------------------------------------
// Selective scan with dt_proj+softplus FUSED (g_delta eliminated).
// Thread d holds dt_proj_w[d,0:16] in registers; delta recomputed identically
// in phase1 and phase3 from broadcast g_xdbl rows -> chunk combine stays exact.
// exp-collapse fast path when A[n] == (n+1)*A[0].
// ---------------------------------------------------------------------------
__device__ __forceinline__ bool a_struct(const float* A) {
    bool f = true;
#pragma unroll
    for (int n = 1; n < NST; n++)
        f &= fabsf(A[n] - (float)(n + 1) * A[0]) <= 1e-5f * (float)(n + 1) * fabsf(A[0]);
    return f;
}

__device__ __forceinline__ float sp_delta(const float* wr, float bv,
                                          const float4* xr) {
    float v = bv;
#pragma unroll
    for (int q = 0; q < 4; q++) {
        float4 dt = __ldg(xr + q);
        v += wr[q*4+0]*dt.x + wr[q*4+1]*dt.y + wr[q*4+2]*dt.z + wr[q*4+3]*dt.w;
    }
    return (v > 20.f) ? v : log1pf(__expf(v));
}

template<bool FAST>
__device__ __forceinline__ void scan1_body(int c, int g, int dir, int d,
                                           const float* A, const float* wr,
                                           float bv, float* h, float& S) {
    const float* uu_ = g_xc   + (size_t)dir * NROWS * CC;
    const float* xd  = g_xdbl + (size_t)dir * NROWS * 32;
    const float A0 = A[0];
    for (int t = 0; t < LCH; t++) {
        int tau = c * LCH + t;
        int l   = (dir == 0) ? tau : (LL - 1 - tau);
        size_t row = (size_t)g * LL + l;
        const float4* xr = (const float4*)(xd + row * 32);
        float dl = sp_delta(wr, bv, xr);
        float uv = uu_[row * CC + d];
        S += dl;
        float du = dl * uv;
        float4 B0 = __ldg(xr + 4), B1 = __ldg(xr + 5);
        const float* Bp = (const float*)&B0;   // B0,B1 contiguous in local
        float Bv[8] = {B0.x, B0.y, B0.z, B0.w, B1.x, B1.y, B1.z, B1.w};
        (void)Bp;
        if (FAST) {
            float p = __expf(dl * A0);
            float e = p;
#pragma unroll
            for (int n = 0; n < NST; n++) { h[n] = e * h[n] + du * Bv[n]; e *= p; }
        } else {
#pragma unroll
            for (int n = 0; n < NST; n++)
                h[n] = __expf(dl * A[n]) * h[n] + du * Bv[n];
        }
    }
}

__global__ void scan_phase1(const float* __restrict__ Alog_f,
                            const float* __restrict__ Alog_b,
                            const float* __restrict__ dtw,
                            const float* __restrict__ dtb) {
    int c = blockIdx.x, g = blockIdx.y, dir = blockIdx.z;
    int d = threadIdx.x;
    const float* Alog = dir ? Alog_b : Alog_f;
    float A[NST];
#pragma unroll
    for (int n = 0; n < NST; n++) A[n] = -__expf(Alog[d * NST + n]);
    float wr[RNK];
#pragma unroll
    for (int q = 0; q < 4; q++) {
        float4 w4 = __ldg((const float4*)(dtw + d * RNK) + q);
        wr[q*4+0] = w4.x; wr[q*4+1] = w4.y; wr[q*4+2] = w4.z; wr[q*4+3] = w4.w;
    }
    float bv = dtb[d];
    float h[NST];
#pragma unroll
    for (int n = 0; n < NST; n++) h[n] = 0.f;
    float S = 0.f;

    if (a_struct(A)) scan1_body<true>(c, g, dir, d, A, wr, bv, h, S);
    else             scan1_body<false>(c, g, dir, d, A, wr, bv, h, S);

    size_t base = ((size_t)dir * GG * NCH + (size_t)g * NCH + c) * CC + d;
#pragma unroll
    for (int n = 0; n < NST; n++) g_hloc[base * NST + n] = h[n];
    g_S[base] = S;
}

__global__ void scan_phase2(const float* __restrict__ Alog_f,
                            const float* __restrict__ Alog_b) {
    int t = blockIdx.x * 256 + threadIdx.x;
    int n   = t & 7;
    int d   = (t >> 3) & 255;
    int g   = (t >> 11) & 7;
    int dir = t >> 14;
    const float* Alog = dir ? Alog_b : Alog_f;
    float A = -__expf(Alog[d * NST + n]);
    float h = 0.f;
    for (int c = 0; c < NCH; c++) {
        size_t base = ((size_t)dir * GG * NCH + (size_t)g * NCH + c) * CC + d;
        g_hini[base * NST + n] = h;
        float S = g_S[base];
        h = __expf(A * S) * h + g_hloc[base * NST + n];
    }
}

template<bool FAST>
__device__ __forceinline__ void scan3_body(int c, int g, int dir, int d,
                                           const float* A, const float* wr,
                                           float bv, float* h, float Dv) {
    const float* uu_ = g_xc   + (size_t)dir * NROWS * CC;
    const float* xd  = g_xdbl + (size_t)dir * NROWS * 32;
    float* yo        = g_ydir + (size_t)dir * NROWS * CC;
    const float A0 = A[0];
    for (int t = 0; t < LCH; t++) {
        int tau = c * LCH + t;
        int l   = (dir == 0) ? tau : (LL - 1 - tau);
        size_t row = (size_t)g * LL + l;
        const float4* xr = (const float4*)(xd + row * 32);
        float dl = sp_delta(wr, bv, xr);
        float uv = uu_[row * CC + d];
        float du = dl * uv;
        float4 B0 = __ldg(xr + 4), B1 = __ldg(xr + 5);
        float4 C0 = __ldg(xr + 6), C1 = __ldg(xr + 7);
        float Bv[8] = {B0.x, B0.y, B0.z, B0.w, B1.x, B1.y, B1.z, B1.w};
        float Cv[8] = {C0.x, C0.y, C0.z, C0.w, C1.x, C1.y, C1.z, C1.w};
        float y = 0.f;
        if (FAST) {
            float p = __expf(dl * A0);
            float e = p;
#pragma unroll
            for (int n = 0; n < NST; n++) {
                h[n] = e * h[n] + du * Bv[n];
                y += h[n] * Cv[n];
                e *= p;
            }
        } else {
#pragma unroll
            for (int n = 0; n < NST; n++) {
                h[n] = __expf(dl * A[n]) * h[n] + du * Bv[n];
                y += h[n] * Cv[n];
            }
        }
        float z  = g_xz[row * (2 * CC) + CC + d];
        float sz = z / (1.0f + __expf(-z));
        yo[row * CC + d] = tf32r(0.5f * (y + Dv * uv) * sz);
    }
}

__global__ void scan_phase3(const float* __restrict__ Alog_f,
                            const float* __restrict__ Alog_b,
                            const float* __restrict__ dtw,
                            const float* __restrict__ dtb,
                            const float* __restrict__ Dp) {
    int c = blockIdx.x, g = blockIdx.y, dir = blockIdx.z;
    int d = threadIdx.x;
    const float* Alog = dir ? Alog_b : Alog_f;
    float A[NST];
#pragma unroll
    for (int n = 0; n < NST; n++) A[n] = -__expf(Alog[d * NST + n]);
    float wr[RNK];
#pragma unroll
    for (int q = 0; q < 4; q++) {
        float4 w4 = __ldg((const float4*)(dtw + d * RNK) + q);
        wr[q*4+0] = w4.x; wr[q*4+1] = w4.y; wr[q*4+2] = w4.z; wr[q*4+3] = w4.w;
    }
    float bv = dtb[d];
    float Dv = Dp[d];
    size_t base = ((size_t)dir * GG * NCH + (size_t)g * NCH + c) * CC + d;
    float h[NST];
#pragma unroll
    for (int n = 0; n < NST; n++) h[n] = g_hini[base * NST + n];

    if (a_struct(A)) scan3_body<true>(c, g, dir, d, A, wr, bv, h, Dv);
    else             scan3_body<false>(c, g, dir, d, A, wr, bv, h, Dv);
}

// ---------------------------------------------------------------------------
// Host launcher — kernel launches only.
// ---------------------------------------------------------------------------
extern "C" void kernel_launch(void* const* d_in, const int* in_sizes, int n_in,
                              void* d_out, int out_size) {
    const float* data  = (const float*)d_in[0];
    const float* ln_w  = (const float*)d_in[1];
    const float* ln_b  = (const float*)d_in[2];
    const float* inpw  = (const float*)d_in[3];
    const float* convw = (const float*)d_in[4];
    const float* convb = (const float*)d_in[5];
    const float* xprw  = (const float*)d_in[6];
    const float* dtw   = (const float*)d_in[7];
    const float* dtb   = (const float*)d_in[8];
    const float* Alog  = (const float*)d_in[9];
    const float* Ablog = (const float*)d_in[10];
    const float* Dmat  = (const float*)d_in[11];
    const float* outw  = (const float*)d_in[12];
    const float* mn_w  = (const float*)d_in[13];
    const float* mn_b  = (const float*)d_in[14];
    const int*   rl    = (const int*)  d_in[15];

    dim3 tposeGrid(LL / 32, CC / 32, GG);
    dim3 tposeBlk(32, 8);

    wprep<<<(NIN + NXP + NOUT + 255) / 256, 256>>>(inpw, xprw, outw);
    mean_kernel<<<tposeGrid, tposeBlk>>>(data, rl);
    ln_fused<0, 1><<<NROWS / 8, 256>>>(nullptr, nullptr, ln_w, ln_b);

    for (int i = 0; i < DEPTHN; i++) {
        const float* cw_i   = convw + i * CC * 4;
        const float* cb_i   = convb + i * CC;
        const float* dtw_i  = dtw   + (size_t)i * CC * RNK;
        const float* dtb_i  = dtb   + i * CC;
        const float* Al_i   = Alog  + (size_t)i * CC * NST;
        const float* Ab_i   = Ablog + (size_t)i * CC * NST;
        const float* D_i    = Dmat  + i * CC;
        const float* mnw_i  = mn_w  + i * CC;
        const float* mnb_i  = mn_b  + i * CC;

        tc_gemm<0, 128><<<dim3(512 / 128, NROWS / 128), 256>>>(i);
        conv_silu_kernel<<<(2 * NROWS * CC) / (256 * 4), 256>>>(cw_i, cb_i);
        tc_gemm<1, 32><<<dim3(1, NROWS / 128, 2), 256>>>(i);
        scan_phase1<<<dim3(NCH, GG, 2), 256>>>(Al_i, Ab_i, dtw_i, dtb_i);
        scan_phase2<<<(2 * GG * CC * NST) / 256, 256>>>(Al_i, Ab_i);
        scan_phase3<<<dim3(NCH, GG, 2), 256>>>(Al_i, Ab_i, dtw_i, dtb_i, D_i);
        tc_gemm<2, 128><<<dim3(256 / 128, NROWS / 128), 256>>>(i);
        if (i < DEPTHN - 1)
            ln_fused<1, 1><<<NROWS / 8, 256>>>(mnw_i, mnb_i,
                                               ln_w + (i + 1) * CC, ln_b + (i + 1) * CC);
        else
            ln_fused<1, 0><<<NROWS / 8, 256>>>(mnw_i, mnb_i, nullptr, nullptr);
    }

    out_transpose<<<tposeGrid, tposeBlk>>>((float*)d_out);
}

// round 10
// speedup vs baseline: 1.0345x; 1.0345x over previous
#include <cuda_runtime.h>
#include <cstdint>

// ---------------------------------------------------------------------------
// Problem constants
// ---------------------------------------------------------------------------
#define GG      8
#define LL      4096
#define CC      256
#define NST     8
#define RNK     16
#define DEPTHN  4
#define NROWS   (GG*LL)
#define LCH     64
#define NCH     (LL/LCH)

// ---------------------------------------------------------------------------
// Scratch (device globals) — referenced ONLY from device code
// ---------------------------------------------------------------------------
__device__ float g_x    [NROWS*CC];
__device__ float g_xn   [NROWS*CC];
__device__ float g_xz   [NROWS*2*CC];
__device__ float g_xc   [2*NROWS*CC];
__device__ float g_xdbl [2*NROWS*32];
__device__ float g_delta[2*NROWS*CC];
__device__ float g_pexp [2*NROWS*CC];   // exp(delta * A0) precomputed
__device__ float g_sz   [NROWS*CC];     // 0.5 * silu(z) precomputed
__device__ float g_ydir [2*NROWS*CC];
__device__ float g_hloc [2*GG*NCH*CC*NST];
__device__ float g_hini [2*GG*NCH*CC*NST];
__device__ float g_S    [2*GG*NCH*CC];
__device__ float g_win  [DEPTHN*2*CC*CC];
__device__ float g_wxp  [DEPTHN*32*CC];
__device__ float g_wout [DEPTHN*CC*CC];

__device__ __forceinline__ unsigned f2tf(float x) {
    unsigned r;
    asm("cvt.rna.tf32.f32 %0, %1;" : "=r"(r) : "f"(x));
    return r;
}
__device__ __forceinline__ float tf32r(float x) { return __uint_as_float(f2tf(x)); }

// ---------------------------------------------------------------------------
// one-shot weight prep: round all layers' GEMM weights to tf32
// ---------------------------------------------------------------------------
#define NIN  (DEPTHN*2*CC*CC)
#define NXP  (DEPTHN*32*CC)
#define NOUT (DEPTHN*CC*CC)
__global__ void wprep(const float* __restrict__ inpw,
                      const float* __restrict__ xpw,
                      const float* __restrict__ outw) {
    int i = blockIdx.x * 256 + threadIdx.x;
    if (i < NIN)                    g_win[i]          = tf32r(inpw[i]);
    else if (i < NIN + NXP)         g_wxp[i - NIN]    = tf32r(xpw[i - NIN]);
    else if (i < NIN + NXP + NOUT)  g_wout[i-NIN-NXP] = tf32r(outw[i-NIN-NXP]);
}

// ---------------------------------------------------------------------------
// mean + transpose: data (B,C,HW) -> g_x (g,l,c)
// ---------------------------------------------------------------------------
__global__ void mean_kernel(const float* __restrict__ data,
                            const int* __restrict__ rl) {
    __shared__ float tile[32][33];
    int g  = blockIdx.z;
    int c0 = blockIdx.y * 32;
    int l0 = blockIdx.x * 32;
    int off = 0;
    for (int i = 0; i < g; i++) off += rl[i];
    int cnt = rl[g];
    float inv = 1.0f / (float)cnt;
    for (int cc = threadIdx.y; cc < 32; cc += 8) {
        int c = c0 + cc;
        int l = l0 + threadIdx.x;
        float s = 0.f;
        for (int a = 0; a < cnt; a++)
            s += data[((size_t)(off + a) * CC + c) * LL + l];
        tile[cc][threadIdx.x] = s * inv;
    }
    __syncthreads();
    for (int lc = threadIdx.y; lc < 32; lc += 8) {
        int l = l0 + lc;
        int c = c0 + threadIdx.x;
        g_x[((size_t)g * LL + l) * CC + c] = tile[threadIdx.x][lc];
    }
}

__global__ void out_transpose(float* __restrict__ out) {
    __shared__ float tile[32][33];
    int g  = blockIdx.z;
    int c0 = blockIdx.y * 32;
    int l0 = blockIdx.x * 32;
    for (int lc = threadIdx.y; lc < 32; lc += 8)
        tile[threadIdx.x][lc] = g_x[((size_t)g * LL + l0 + lc) * CC + c0 + threadIdx.x];
    __syncthreads();
    for (int cc = threadIdx.y; cc < 32; cc += 8)
        out[((size_t)g * CC + c0 + cc) * LL + l0 + threadIdx.x] = tile[cc][threadIdx.x];
}

// ---------------------------------------------------------------------------
// Fused LayerNorm (warp per row).
// POST: x := LN(g_xn)*wp+bp + g_x ; PRE: g_xn := tf32(LN(x)*wq+bq)
// ---------------------------------------------------------------------------
template<int POST, int PRE>
__global__ void ln_fused(const float* __restrict__ wp, const float* __restrict__ bp,
                         const float* __restrict__ wq, const float* __restrict__ bq) {
    int row  = blockIdx.x * 8 + (threadIdx.x >> 5);
    int lane = threadIdx.x & 31;
    float v[8];
    if (POST) {
        const float* r = g_xn + (size_t)row * CC;
        float s = 0.f, s2 = 0.f;
#pragma unroll
        for (int k = 0; k < 8; k++) {
            v[k] = r[k * 32 + lane];
            s += v[k]; s2 += v[k] * v[k];
        }
#pragma unroll
        for (int o = 16; o; o >>= 1) {
            s  += __shfl_xor_sync(0xffffffffu, s,  o);
            s2 += __shfl_xor_sync(0xffffffffu, s2, o);
        }
        float mu  = s * (1.0f / CC);
        float var = s2 * (1.0f / CC) - mu * mu;
        float inv = rsqrtf(var + 1e-5f);
#pragma unroll
        for (int k = 0; k < 8; k++) {
            int cc = k * 32 + lane;
            v[k] = (v[k] - mu) * inv * wp[cc] + bp[cc] + g_x[(size_t)row * CC + cc];
            g_x[(size_t)row * CC + cc] = v[k];
        }
    } else {
        const float* r = g_x + (size_t)row * CC;
#pragma unroll
        for (int k = 0; k < 8; k++) v[k] = r[k * 32 + lane];
    }
    if (PRE) {
        float s = 0.f, s2 = 0.f;
#pragma unroll
        for (int k = 0; k < 8; k++) { s += v[k]; s2 += v[k] * v[k]; }
#pragma unroll
        for (int o = 16; o; o >>= 1) {
            s  += __shfl_xor_sync(0xffffffffu, s,  o);
            s2 += __shfl_xor_sync(0xffffffffu, s2, o);
        }
        float mu  = s * (1.0f / CC);
        float var = s2 * (1.0f / CC) - mu * mu;
        float inv = rsqrtf(var + 1e-5f);
#pragma unroll
        for (int k = 0; k < 8; k++) {
            int cc = k * 32 + lane;
            g_xn[(size_t)row * CC + cc] = tf32r((v[k] - mu) * inv * wq[cc] + bq[cc]);
        }
    }
}

// ---------------------------------------------------------------------------
// cp.async helpers
// ---------------------------------------------------------------------------
__device__ __forceinline__ void cp16(void* dst_smem, const void* src) {
    uint32_t d = (uint32_t)__cvta_generic_to_shared(dst_smem);
    asm volatile("cp.async.cg.shared.global [%0], [%1], 16;" :: "r"(d), "l"(src));
}
#define CP_COMMIT() asm volatile("cp.async.commit_group;" ::: "memory")
#define CP_WAIT(n)  asm volatile("cp.async.wait_group %0;" :: "n"(n) : "memory")

// ---------------------------------------------------------------------------
// 3-stage pipelined tf32 tensor-core GEMM (in_proj / out_proj only).
// MODE 0: in_proj   A=g_xn (tf32), C=g_xz (Nn=512), KT=16
// MODE 2: out_proj  virtual K=512 over ydir fwd|bwd (pre-halved), C=g_xn, KT=32
// ---------------------------------------------------------------------------
template<int MODE, int BN>
__global__ void __launch_bounds__(256)
tc_gemm(int layer) {
    constexpr int BM = 128;
    constexpr int BK = 16;
    constexpr int SW = BK + 4;
    constexpr int KT = (MODE == 2) ? 32 : 16;
    constexpr int WARPS_N = 4;
    constexpr int WM = BM / 2;
    constexpr int WN = BN / 4;
    constexpr int MT = WM / 16;
    constexpr int NT = WN / 8;

    __shared__ float As[3][BM * SW];
    __shared__ float Bs[3][BN * SW];

    const int tid  = threadIdx.x;
    const int lane = tid & 31;
    const int warp = tid >> 5;
    const int bm   = blockIdx.y * BM;
    const int bn   = blockIdx.x * BN;
    const int wm   = (warp / WARPS_N) * WM;
    const int wn   = (warp % WARPS_N) * WN;

    const float* A0;
    const float* W;
    float* Cout;
    int Nn;
    if (MODE == 0) { A0 = g_xn;  W = g_win + (size_t)layer * 2 * CC * CC;
                     Cout = g_xz;  Nn = 2 * CC; }
    else           { A0 = g_ydir; W = g_wout + (size_t)layer * CC * CC;
                     Cout = g_xn; Nn = CC; }

    auto stage = [&](int s, int kc) {
        const float* Ap = A0;
        if (MODE == 2 && kc >= 16) Ap = g_ydir + (size_t)NROWS * CC;
        const int k0 = (kc & 15) * BK;
        for (int idx = tid; idx < BM * 4; idx += 256) {
            int r = idx >> 2, q = idx & 3;
            cp16(&As[s][r * SW + q * 4], Ap + (size_t)(bm + r) * CC + k0 + q * 4);
        }
        for (int idx = tid; idx < BN * 4; idx += 256) {
            int r = idx >> 2, q = idx & 3;
            cp16(&Bs[s][r * SW + q * 4], W + (size_t)(bn + r) * CC + k0 + q * 4);
        }
    };

    float c[MT][NT][4];
#pragma unroll
    for (int i = 0; i < MT; i++)
#pragma unroll
        for (int j = 0; j < NT; j++)
#pragma unroll
            for (int q = 0; q < 4; q++) c[i][j][q] = 0.f;

    stage(0, 0); CP_COMMIT();
    stage(1, 1); CP_COMMIT();

#pragma unroll 1
    for (int kc = 0; kc < KT; kc++) {
        if (kc == KT - 1) { CP_WAIT(0); } else { CP_WAIT(1); }
        __syncthreads();

        const float* as_ = As[kc % 3];
        const float* bs_ = Bs[kc % 3];
#pragma unroll
        for (int ks = 0; ks < BK / 8; ks++) {
            const int kk = ks * 8 + (lane & 3);
            unsigned a[MT][4], bf[NT][2];
#pragma unroll
            for (int i = 0; i < MT; i++) {
                int r0 = wm + i * 16 + (lane >> 2);
                a[i][0] = __float_as_uint(as_[r0 * SW + kk]);
                a[i][1] = __float_as_uint(as_[(r0 + 8) * SW + kk]);
                a[i][2] = __float_as_uint(as_[r0 * SW + kk + 4]);
                a[i][3] = __float_as_uint(as_[(r0 + 8) * SW + kk + 4]);
            }
#pragma unroll
            for (int j = 0; j < NT; j++) {
                int n0 = wn + j * 8 + (lane >> 2);
                bf[j][0] = __float_as_uint(bs_[n0 * SW + kk]);
                bf[j][1] = __float_as_uint(bs_[n0 * SW + kk + 4]);
            }
#pragma unroll
            for (int i = 0; i < MT; i++)
#pragma unroll
                for (int j = 0; j < NT; j++) {
                    asm volatile(
                        "mma.sync.aligned.m16n8k8.row.col.f32.tf32.tf32.f32 "
                        "{%0,%1,%2,%3}, {%4,%5,%6,%7}, {%8,%9}, {%0,%1,%2,%3};"
                        : "+f"(c[i][j][0]), "+f"(c[i][j][1]),
                          "+f"(c[i][j][2]), "+f"(c[i][j][3])
                        : "r"(a[i][0]), "r"(a[i][1]), "r"(a[i][2]), "r"(a[i][3]),
                          "r"(bf[j][0]), "r"(bf[j][1]));
                }
        }
        __syncthreads();
        if (kc + 2 < KT) { stage((kc + 2) % 3, kc + 2); CP_COMMIT(); }
    }

#pragma unroll
    for (int i = 0; i < MT; i++) {
        int r0 = bm + wm + i * 16 + (lane >> 2);
#pragma unroll
        for (int j = 0; j < NT; j++) {
            int c0 = bn + wn + j * 8 + 2 * (lane & 3);
            *(float2*)(Cout + (size_t)r0 * Nn + c0)       = make_float2(c[i][j][0], c[i][j][1]);
            *(float2*)(Cout + (size_t)(r0 + 8) * Nn + c0) = make_float2(c[i][j][2], c[i][j][3]);
        }
    }
}

// ---------------------------------------------------------------------------
// Fused conv+SiLU + x_proj GEMM.  grid (NROWS/128, 2 dirs), 256 threads.
// Stages A-tiles by computing causal conv + SiLU directly from g_xz, writes
// xc to g_xc (side effect, each element exactly once), runs N=32 tf32 MMA
// with the whole weight matrix resident in smem.  Replaces conv kernel +
// MODE-1 GEMM.
// ---------------------------------------------------------------------------
__global__ void __launch_bounds__(256)
xp_conv_gemm(int layer, const float* __restrict__ cw, const float* __restrict__ cb) {
    constexpr int BM = 128, BK = 16, SW = BK + 4;
    __shared__ float As[2][BM * SW];
    __shared__ float Bs[32][CC + 4];
    __shared__ float Cw[CC * 4];
    __shared__ float Cb[CC];

    const int tid  = threadIdx.x;
    const int lane = tid & 31;
    const int warp = tid >> 5;
    const int bm   = blockIdx.x * BM;
    const int dir  = blockIdx.y;
    const float* W = g_wxp + (size_t)layer * 32 * CC;

    for (int i = tid; i < 32 * (CC / 4); i += 256) {
        int r = i / (CC / 4), q = i % (CC / 4);
        *(float4*)&Bs[r][q * 4] = *(const float4*)(W + r * CC + q * 4);
    }
    for (int i = tid; i < CC * 4; i += 256) Cw[i] = cw[i];
    for (int i = tid; i < CC; i += 256)     Cb[i] = cb[i];
    __syncthreads();

    float c[4][4];
#pragma unroll
    for (int j = 0; j < 4; j++)
#pragma unroll
        for (int q = 0; q < 4; q++) c[j][q] = 0.f;

    const int l_of_bm = bm & (LL - 1);
    const size_t gbase = (size_t)(bm - l_of_bm) * (2 * CC);  // g*LL*(2C)

#pragma unroll 1
    for (int kc = 0; kc < 16; kc++) {
        const int k0 = kc * BK;
        const int s  = kc & 1;
        // ---- fused conv+silu staging ----
        for (int idx = tid; idx < BM * 4; idx += 256) {
            int r  = idx >> 2, q = idx & 3;
            int row = bm + r;
            int l   = row & (LL - 1);
            int c0  = k0 + q * 4;
            float4 acc = *(const float4*)(Cb + c0);
#pragma unroll
            for (int j = 0; j < 4; j++) {
                int ls = (dir == 0) ? (l - 3 + j) : (l + 3 - j);
                if (ls >= 0 && ls < LL) {
                    const float4 xv = *(const float4*)(g_xz + gbase +
                                                       (size_t)ls * (2 * CC) + c0);
                    acc.x += Cw[(c0 + 0) * 4 + j] * xv.x;
                    acc.y += Cw[(c0 + 1) * 4 + j] * xv.y;
                    acc.z += Cw[(c0 + 2) * 4 + j] * xv.z;
                    acc.w += Cw[(c0 + 3) * 4 + j] * xv.w;
                }
            }
            acc.x = acc.x / (1.0f + __expf(-acc.x));
            acc.y = acc.y / (1.0f + __expf(-acc.y));
            acc.z = acc.z / (1.0f + __expf(-acc.z));
            acc.w = acc.w / (1.0f + __expf(-acc.w));
            *(float4*)(g_xc + (size_t)dir * NROWS * CC + (size_t)row * CC + c0) = acc;
            *(float4*)&As[s][r * SW + q * 4] =
                make_float4(tf32r(acc.x), tf32r(acc.y), tf32r(acc.z), tf32r(acc.w));
        }
        __syncthreads();

#pragma unroll
        for (int ks = 0; ks < 2; ks++) {
            const int kkl = ks * 8 + (lane & 3);
            const int kkg = k0 + kkl;
            int r0 = warp * 16 + (lane >> 2);
            unsigned a0 = __float_as_uint(As[s][r0 * SW + kkl]);
            unsigned a1 = __float_as_uint(As[s][(r0 + 8) * SW + kkl]);
            unsigned a2 = __float_as_uint(As[s][r0 * SW + kkl + 4]);
            unsigned a3 = __float_as_uint(As[s][(r0 + 8) * SW + kkl + 4]);
#pragma unroll
            for (int j = 0; j < 4; j++) {
                int n0 = j * 8 + (lane >> 2);
                unsigned b0 = __float_as_uint(Bs[n0][kkg]);
                unsigned b1 = __float_as_uint(Bs[n0][kkg + 4]);
                asm volatile(
                    "mma.sync.aligned.m16n8k8.row.col.f32.tf32.tf32.f32 "
                    "{%0,%1,%2,%3}, {%4,%5,%6,%7}, {%8,%9}, {%0,%1,%2,%3};"
                    : "+f"(c[j][0]), "+f"(c[j][1]), "+f"(c[j][2]), "+f"(c[j][3])
                    : "r"(a0), "r"(a1), "r"(a2), "r"(a3), "r"(b0), "r"(b1));
            }
        }
        __syncthreads();
    }

    float* Cout = g_xdbl + (size_t)dir * NROWS * 32;
    int r0 = bm + warp * 16 + (lane >> 2);
#pragma unroll
    for (int j = 0; j < 4; j++) {
        int c0 = j * 8 + 2 * (lane & 3);
        *(float2*)(Cout + (size_t)r0 * 32 + c0)       = make_float2(c[j][0], c[j][1]);
        *(float2*)(Cout + (size_t)(r0 + 8) * 32 + c0) = make_float2(c[j][2], c[j][3]);
    }
}

// ---------------------------------------------------------------------------
// dt_proj + softplus; also emits p = exp(dl*A0) and (dir 0) sz = 0.5*silu(z).
// 64 rows/block, weights cached in smem.
// ---------------------------------------------------------------------------
__global__ void dtproj_kernel(const float* __restrict__ dtw,
                              const float* __restrict__ dtb,
                              const float* __restrict__ Alogf,
                              const float* __restrict__ Alogb) {
    __shared__ float swt[RNK][CC];
    __shared__ float sdt[64][RNK + 1];
    const int d   = threadIdx.x;
    const int dir = blockIdx.y;
    const size_t row0 = (size_t)blockIdx.x * 64;

    for (int i = threadIdx.x; i < CC * RNK; i += 256) {
        int dd = i >> 4, r = i & 15;
        swt[r][dd] = dtw[i];
    }
    const float* xb = g_xdbl + (size_t)dir * NROWS * 32 + row0 * 32;
    for (int i = threadIdx.x; i < 64 * RNK; i += 256) {
        int t = i >> 4, r = i & 15;
        sdt[t][r] = xb[t * 32 + r];
    }
    __syncthreads();

    float wr[RNK];
#pragma unroll
    for (int r = 0; r < RNK; r++) wr[r] = swt[r][d];
    const float bv = dtb[d];
    const float A0 = -__expf((dir ? Alogb : Alogf)[d * NST]);

    float* dout = g_delta + (size_t)dir * NROWS * CC + row0 * CC + d;
    float* pout = g_pexp  + (size_t)dir * NROWS * CC + row0 * CC + d;
    for (int t = 0; t < 64; t++) {
        float v = bv;
#pragma unroll
        for (int r = 0; r < RNK; r++) v += wr[r] * sdt[t][r];
        v = (v > 20.f) ? v : log1pf(__expf(v));
        dout[t * CC] = v;
        pout[t * CC] = __expf(v * A0);
    }
    if (dir == 0) {
        for (int t = 0; t < 64; t++) {
            float z = g_xz[(row0 + t) * (2 * CC) + CC + d];
            g_sz[(row0 + t) * CC + d] = 0.5f * z / (1.0f + __expf(-z));
        }
    }
}

// ---------------------------------------------------------------------------
// Selective scan (3 phases).  FAST path (A[n] == (n+1)A[0], runtime-verified):
// uses precomputed p from g_pexp — zero transcendentals in the loop.
// ---------------------------------------------------------------------------
__device__ __forceinline__ bool a_struct(const float* A) {
    bool f = true;
#pragma unroll
    for (int n = 1; n < NST; n++)
        f &= fabsf(A[n] - (float)(n + 1) * A[0]) <= 1e-5f * (float)(n + 1) * fabsf(A[0]);
    return f;
}

template<bool FAST>
__device__ __forceinline__ void scan1_body(int c, int g, int dir, int d,
                                           const float* A, float* h, float& S) {
    const float* del = g_delta + (size_t)dir * NROWS * CC;
    const float* pex = g_pexp  + (size_t)dir * NROWS * CC;
    const float* uu_ = g_xc    + (size_t)dir * NROWS * CC;
    const float* xd  = g_xdbl  + (size_t)dir * NROWS * 32;
    for (int t = 0; t < LCH; t++) {
        int tau = c * LCH + t;
        int l   = (dir == 0) ? tau : (LL - 1 - tau);
        size_t row = (size_t)g * LL + l;
        float dl = del[row * CC + d];
        float uv = uu_[row * CC + d];
        S += dl;
        float du = dl * uv;
        const float4* xr = (const float4*)(xd + row * 32);
        float4 B0 = __ldg(xr + 4), B1 = __ldg(xr + 5);
        float Bv[8] = {B0.x, B0.y, B0.z, B0.w, B1.x, B1.y, B1.z, B1.w};
        if (FAST) {
            float p = pex[row * CC + d];
            float e = p;
#pragma unroll
            for (int n = 0; n < NST; n++) { h[n] = e * h[n] + du * Bv[n]; e *= p; }
        } else {
#pragma unroll
            for (int n = 0; n < NST; n++)
                h[n] = __expf(dl * A[n]) * h[n] + du * Bv[n];
        }
    }
}

__global__ void scan_phase1(const float* __restrict__ Alog_f,
                            const float* __restrict__ Alog_b) {
    int c = blockIdx.x, g = blockIdx.y, dir = blockIdx.z;
    int d = threadIdx.x;
    const float* Alog = dir ? Alog_b : Alog_f;
    float A[NST];
#pragma unroll
    for (int n = 0; n < NST; n++) A[n] = -__expf(Alog[d * NST + n]);
    float h[NST];
#pragma unroll
    for (int n = 0; n < NST; n++) h[n] = 0.f;
    float S = 0.f;

    if (a_struct(A)) scan1_body<true>(c, g, dir, d, A, h, S);
    else             scan1_body<false>(c, g, dir, d, A, h, S);

    size_t base = ((size_t)dir * GG * NCH + (size_t)g * NCH + c) * CC + d;
#pragma unroll
    for (int n = 0; n < NST; n++) g_hloc[base * NST + n] = h[n];
    g_S[base] = S;
}

__global__ void scan_phase2(const float* __restrict__ Alog_f,
                            const float* __restrict__ Alog_b) {
    int t = blockIdx.x * 256 + threadIdx.x;
    int n   = t & 7;
    int d   = (t >> 3) & 255;
    int g   = (t >> 11) & 7;
    int dir = t >> 14;
    const float* Alog = dir ? Alog_b : Alog_f;
    float A = -__expf(Alog[d * NST + n]);
    float h = 0.f;
    for (int c = 0; c < NCH; c++) {
        size_t base = ((size_t)dir * GG * NCH + (size_t)g * NCH + c) * CC + d;
        g_hini[base * NST + n] = h;
        float S = g_S[base];
        h = __expf(A * S) * h + g_hloc[base * NST + n];
    }
}

template<bool FAST>
__device__ __forceinline__ void scan3_body(int c, int g, int dir, int d,
                                           const float* A, float* h, float Dv) {
    const float* del = g_delta + (size_t)dir * NROWS * CC;
    const float* pex = g_pexp  + (size_t)dir * NROWS * CC;
    const float* uu_ = g_xc    + (size_t)dir * NROWS * CC;
    const float* xd  = g_xdbl  + (size_t)dir * NROWS * 32;
    float* yo        = g_ydir  + (size_t)dir * NROWS * CC;
    for (int t = 0; t < LCH; t++) {
        int tau = c * LCH + t;
        int l   = (dir == 0) ? tau : (LL - 1 - tau);
        size_t row = (size_t)g * LL + l;
        float dl = del[row * CC + d];
        float uv = uu_[row * CC + d];
        float du = dl * uv;
        const float4* xr = (const float4*)(xd + row * 32);
        float4 B0 = __ldg(xr + 4), B1 = __ldg(xr + 5);
        float4 C0 = __ldg(xr + 6), C1 = __ldg(xr + 7);
        float Bv[8] = {B0.x, B0.y, B0.z, B0.w, B1.x, B1.y, B1.z, B1.w};
        float Cv[8] = {C0.x, C0.y, C0.z, C0.w, C1.x, C1.y, C1.z, C1.w};
        float y = 0.f;
        if (FAST) {
            float p = pex[row * CC + d];
            float e = p;
#pragma unroll
            for (int n = 0; n < NST; n++) {
                h[n] = e * h[n] + du * Bv[n];
                y += h[n] * Cv[n];
                e *= p;
            }
        } else {
#pragma unroll
            for (int n = 0; n < NST; n++) {
                h[n] = __expf(dl * A[n]) * h[n] + du * Bv[n];
                y += h[n] * Cv[n];
            }
        }
        float sz = g_sz[row * CC + d];   // pre-halved silu(z)
        yo[row * CC + d] = tf32r((y + Dv * uv) * sz);
    }
}

__global__ void scan_phase3(const float* __restrict__ Alog_f,
                            const float* __restrict__ Alog_b,
                            const float* __restrict__ Dp) {
    int c = blockIdx.x, g = blockIdx.y, dir = blockIdx.z;
    int d = threadIdx.x;
    const float* Alog = dir ? Alog_b : Alog_f;
    float A[NST];
#pragma unroll
    for (int n = 0; n < NST; n++) A[n] = -__expf(Alog[d * NST + n]);
    float Dv = Dp[d];
    size_t base = ((size_t)dir * GG * NCH + (size_t)g * NCH + c) * CC + d;
    float h[NST];
#pragma unroll
    for (int n = 0; n < NST; n++) h[n] = g_hini[base * NST + n];

    if (a_struct(A)) scan3_body<true>(c, g, dir, d, A, h, Dv);
    else             scan3_body<false>(c, g, dir, d, A, h, Dv);
}

// ---------------------------------------------------------------------------
// Host launcher — kernel launches only.
// ---------------------------------------------------------------------------
extern "C" void kernel_launch(void* const* d_in, const int* in_sizes, int n_in,
                              void* d_out, int out_size) {
    const float* data  = (const float*)d_in[0];
    const float* ln_w  = (const float*)d_in[1];
    const float* ln_b  = (const float*)d_in[2];
    const float* inpw  = (const float*)d_in[3];
    const float* convw = (const float*)d_in[4];
    const float* convb = (const float*)d_in[5];
    const float* xprw  = (const float*)d_in[6];
    const float* dtw   = (const float*)d_in[7];
    const float* dtb   = (const float*)d_in[8];
    const float* Alog  = (const float*)d_in[9];
    const float* Ablog = (const float*)d_in[10];
    const float* Dmat  = (const float*)d_in[11];
    const float* outw  = (const float*)d_in[12];
    const float* mn_w  = (const float*)d_in[13];
    const float* mn_b  = (const float*)d_in[14];
    const int*   rl    = (const int*)  d_in[15];

    dim3 tposeGrid(LL / 32, CC / 32, GG);
    dim3 tposeBlk(32, 8);

    wprep<<<(NIN + NXP + NOUT + 255) / 256, 256>>>(inpw, xprw, outw);
    mean_kernel<<<tposeGrid, tposeBlk>>>(data, rl);
    ln_fused<0, 1><<<NROWS / 8, 256>>>(nullptr, nullptr, ln_w, ln_b);

    for (int i = 0; i < DEPTHN; i++) {
        const float* cw_i   = convw + i * CC * 4;
        const float* cb_i   = convb + i * CC;
        const float* dtw_i  = dtw   + (size_t)i * CC * RNK;
        const float* dtb_i  = dtb   + i * CC;
        const float* Al_i   = Alog  + (size_t)i * CC * NST;
        const float* Ab_i   = Ablog + (size_t)i * CC * NST;
        const float* D_i    = Dmat  + i * CC;
        const float* mnw_i  = mn_w  + i * CC;
        const float* mnb_i  = mn_b  + i * CC;

        // in_proj
        tc_gemm<0, 128><<<dim3(512 / 128, NROWS / 128), 256>>>(i);
        // fused conv+silu + x_proj (writes g_xc and g_xdbl)
        xp_conv_gemm<<<dim3(NROWS / 128, 2), 256>>>(i, cw_i, cb_i);
        // dt_proj + softplus + p + sz
        dtproj_kernel<<<dim3(NROWS / 64, 2), 256>>>(dtw_i, dtb_i, Al_i, Ab_i);
        // chunked selective scan
        scan_phase1<<<dim3(NCH, GG, 2), 256>>>(Al_i, Ab_i);
        scan_phase2<<<(2 * GG * CC * NST) / 256, 256>>>(Al_i, Ab_i);
        scan_phase3<<<dim3(NCH, GG, 2), 256>>>(Al_i, Ab_i, D_i);
        // out_proj
        tc_gemm<2, 128><<<dim3(256 / 128, NROWS / 128), 256>>>(i);
        // post-norm + residual (+ next pre-norm)
        if (i < DEPTHN - 1)
            ln_fused<1, 1><<<NROWS / 8, 256>>>(mnw_i, mnb_i,
                                               ln_w + (i + 1) * CC, ln_b + (i + 1) * CC);
        else
            ln_fused<1, 0><<<NROWS / 8, 256>>>(mnw_i, mnb_i, nullptr, nullptr);
    }

    out_transpose<<<tposeGrid, tposeBlk>>>((float*)d_out);
}